// round 5
// baseline (speedup 1.0000x reference)
#include <cuda_runtime.h>
#include <cstdint>
#include <cstddef>

#define D_MODEL 1024
#define D_FF    4096
#define HEADS   16
#define DKH     64
#define BATCH   2
#define SEQ     2048
#define NTOK    (BATCH*SEQ)

// ---------------- scratch (device globals; no allocations allowed) ----------
__device__ float g_h1[NTOK * D_MODEL];
__device__ float g_q [NTOK * D_MODEL];
__device__ float g_k [NTOK * D_MODEL];
__device__ float g_v [NTOK * D_MODEL];
__device__ float g_at[NTOK * D_MODEL];
__device__ float g_x1[NTOK * D_MODEL];
__device__ float g_h2[NTOK * D_MODEL];
__device__ float g_f1[NTOK * D_FF];
// pre-rounded (tf32) weight copies
__device__ float g_wq[D_MODEL * D_MODEL];
__device__ float g_wk[D_MODEL * D_MODEL];
__device__ float g_wv[D_MODEL * D_MODEL];
__device__ float g_wo[D_MODEL * D_MODEL];
__device__ float g_w1[D_FF * D_MODEL];
__device__ float g_w2[D_MODEL * D_FF];

// ---------------- helpers ---------------------------------------------------
__device__ __forceinline__ uint32_t smem_u32(const void* p) {
    return (uint32_t)__cvta_generic_to_shared(p);
}
#define CP_ASYNC16(dst, src) \
    asm volatile("cp.async.cg.shared.global [%0], [%1], 16;\n" :: "r"(dst), "l"(src))
#define CP_COMMIT() asm volatile("cp.async.commit_group;\n" ::: "memory")
#define CP_WAIT(n)  asm volatile("cp.async.wait_group %0;\n" :: "n"(n) : "memory")

#define MMA_TF32(d, a, b) \
    asm volatile("mma.sync.aligned.m16n8k8.row.col.f32.tf32.tf32.f32 " \
                 "{%0,%1,%2,%3},{%4,%5,%6,%7},{%8,%9},{%0,%1,%2,%3};" \
                 : "+f"(d[0]), "+f"(d[1]), "+f"(d[2]), "+f"(d[3]) \
                 : "r"(a[0]), "r"(a[1]), "r"(a[2]), "r"(a[3]), \
                   "r"(b[0]), "r"(b[1]))

__device__ __forceinline__ uint32_t f2tf32(float x) {
    uint32_t r;
    asm("cvt.rna.tf32.f32 %0, %1;" : "=r"(r) : "f"(x));
    return r;
}
__device__ __forceinline__ float rnd_tf32(float x) {
    return __uint_as_float(f2tf32(x));
}

// ---------------- round-copy: weights -> tf32-rounded scratch ---------------
__global__ __launch_bounds__(256) void round_copy(const float4* __restrict__ in,
                                                  float4* __restrict__ out, int n4)
{
    int i = blockIdx.x * 256 + threadIdx.x;
    if (i < n4) {
        float4 v = in[i];
        out[i] = make_float4(rnd_tf32(v.x), rnd_tf32(v.y),
                             rnd_tf32(v.z), rnd_tf32(v.w));
    }
}

// ---------------- LayerNorm (output tf32-rounded; feeds GEMM A) ------------
__global__ __launch_bounds__(256) void ln_kernel(const float* __restrict__ x,
                                                 const float* __restrict__ g,
                                                 const float* __restrict__ b,
                                                 float* __restrict__ out)
{
    __shared__ float red[8];
    __shared__ float bcast;
    const int row = blockIdx.x;
    const int t = threadIdx.x;
    const int lane = t & 31, w = t >> 5;

    const float4* x4 = (const float4*)x + (size_t)row * 256;
    float4 v = x4[t];

    float s = v.x + v.y + v.z + v.w;
    #pragma unroll
    for (int o = 16; o; o >>= 1) s += __shfl_xor_sync(0xffffffffu, s, o);
    if (lane == 0) red[w] = s;
    __syncthreads();
    if (t == 0) {
        float tot = 0.f;
        #pragma unroll
        for (int i = 0; i < 8; i++) tot += red[i];
        bcast = tot * (1.f / 1024.f);
    }
    __syncthreads();
    const float mu = bcast;

    float4 d = make_float4(v.x - mu, v.y - mu, v.z - mu, v.w - mu);
    float vs = d.x*d.x + d.y*d.y + d.z*d.z + d.w*d.w;
    __syncthreads();
    #pragma unroll
    for (int o = 16; o; o >>= 1) vs += __shfl_xor_sync(0xffffffffu, vs, o);
    if (lane == 0) red[w] = vs;
    __syncthreads();
    if (t == 0) {
        float tot = 0.f;
        #pragma unroll
        for (int i = 0; i < 8; i++) tot += red[i];
        bcast = rsqrtf(tot * (1.f / 1024.f) + 1e-5f);
    }
    __syncthreads();
    const float rs = bcast;

    float4 gv = ((const float4*)g)[t];
    float4 bv = ((const float4*)b)[t];
    float4 o4 = make_float4(rnd_tf32(d.x*rs*gv.x + bv.x),
                            rnd_tf32(d.y*rs*gv.y + bv.y),
                            rnd_tf32(d.z*rs*gv.z + bv.z),
                            rnd_tf32(d.w*rs*gv.w + bv.w));
    (((float4*)out) + (size_t)row * 256)[t] = o4;
}

// ---------------- TF32 tensor-core GEMM NT ---------------------------------
// C[N,M] = A[N,K] * B[M,K]^T.  Operands PRE-ROUNDED to tf32 (no inner cvt).
// 128x128 tile, BK=32, 256 thr, 2x4 warp grid, 64x32 per warp (4x4 m16n8k8).
// cp.async double-buffered (dynamic smem 72KB).
// EPI: 0=none, 1=+bias[m], 2=+res[n,m], 3=relu(+bias[m])+res[n,m]
// RND: round C to tf32 at store (when C feeds another mma as operand)
#define GBK   32
#define GLDS  36                       // 32 + 4 pad
#define GSTG  (128*GLDS)               // floats per stage per matrix
#define GSMEM_BYTES (4*GSTG*4)         // 2 matrices x 2 stages

template<int EPI, int RND>
__global__ __launch_bounds__(256) void gemm_tf32(const float* __restrict__ A,
                                                 const float* __restrict__ B,
                                                 float* __restrict__ C,
                                                 int N, int M, int K,
                                                 const float* __restrict__ bias,
                                                 const float* __restrict__ res)
{
    extern __shared__ float sh[];
    // layout: As[2][128][36], Bs[2][128][36]
    float* AsB = sh;
    float* BsB = sh + 2 * GSTG;

    const int t    = threadIdx.x;
    const int lane = t & 31;
    const int warp = t >> 5;
    const int wm   = warp >> 2;
    const int wn   = warp & 3;
    const int g    = lane >> 2;
    const int tig  = lane & 3;
    const int n0   = blockIdx.y * 128;
    const int m0   = blockIdx.x * 128;

    const int lr  = t >> 2;            // 0..63
    const int c8  = (t & 3) * 8;       // 0,8,16,24

    const float* Ar0 = A + (size_t)(n0 + lr)      * K + c8;
    const float* Ar1 = A + (size_t)(n0 + lr + 64) * K + c8;
    const float* Br0 = B + (size_t)(m0 + lr)      * K + c8;
    const float* Br1 = B + (size_t)(m0 + lr + 64) * K + c8;

    float acc[4][4][4];
    #pragma unroll
    for (int i = 0; i < 4; i++)
        #pragma unroll
        for (int j = 0; j < 4; j++)
            #pragma unroll
            for (int c = 0; c < 4; c++) acc[i][j][c] = 0.f;

    const int nK = K / GBK;

    // prologue: stage 0
    {
        float* As = AsB; float* Bs = BsB;
        CP_ASYNC16(smem_u32(&As[lr*GLDS + c8]),          Ar0);
        CP_ASYNC16(smem_u32(&As[lr*GLDS + c8 + 4]),      Ar0 + 4);
        CP_ASYNC16(smem_u32(&As[(lr+64)*GLDS + c8]),     Ar1);
        CP_ASYNC16(smem_u32(&As[(lr+64)*GLDS + c8 + 4]), Ar1 + 4);
        CP_ASYNC16(smem_u32(&Bs[lr*GLDS + c8]),          Br0);
        CP_ASYNC16(smem_u32(&Bs[lr*GLDS + c8 + 4]),      Br0 + 4);
        CP_ASYNC16(smem_u32(&Bs[(lr+64)*GLDS + c8]),     Br1);
        CP_ASYNC16(smem_u32(&Bs[(lr+64)*GLDS + c8 + 4]), Br1 + 4);
        CP_COMMIT();
    }

    for (int kt = 0; kt < nK; kt++) {
        const int cur = kt & 1;
        if (kt + 1 < nK) {
            const int nxt = cur ^ 1;
            const int ko = (kt + 1) * GBK;
            float* As = AsB + nxt * GSTG;
            float* Bs = BsB + nxt * GSTG;
            CP_ASYNC16(smem_u32(&As[lr*GLDS + c8]),          Ar0 + ko);
            CP_ASYNC16(smem_u32(&As[lr*GLDS + c8 + 4]),      Ar0 + ko + 4);
            CP_ASYNC16(smem_u32(&As[(lr+64)*GLDS + c8]),     Ar1 + ko);
            CP_ASYNC16(smem_u32(&As[(lr+64)*GLDS + c8 + 4]), Ar1 + ko + 4);
            CP_ASYNC16(smem_u32(&Bs[lr*GLDS + c8]),          Br0 + ko);
            CP_ASYNC16(smem_u32(&Bs[lr*GLDS + c8 + 4]),      Br0 + ko + 4);
            CP_ASYNC16(smem_u32(&Bs[(lr+64)*GLDS + c8]),     Br1 + ko);
            CP_ASYNC16(smem_u32(&Bs[(lr+64)*GLDS + c8 + 4]), Br1 + ko + 4);
            CP_COMMIT();
            CP_WAIT(1);
        } else {
            CP_WAIT(0);
        }
        __syncthreads();

        const float* As = AsB + cur * GSTG;
        const float* Bs = BsB + cur * GSTG;

        #pragma unroll
        for (int ks = 0; ks < 4; ks++) {
            const int kc = ks * 8;
            uint32_t af[4][4];
            #pragma unroll
            for (int mt = 0; mt < 4; mt++) {
                const int r = wm * 64 + mt * 16 + g;
                af[mt][0] = __float_as_uint(As[r*GLDS + kc + tig]);
                af[mt][1] = __float_as_uint(As[(r+8)*GLDS + kc + tig]);
                af[mt][2] = __float_as_uint(As[r*GLDS + kc + 4 + tig]);
                af[mt][3] = __float_as_uint(As[(r+8)*GLDS + kc + 4 + tig]);
            }
            uint32_t bf[4][2];
            #pragma unroll
            for (int nt = 0; nt < 4; nt++) {
                const int c = wn * 32 + nt * 8 + g;
                bf[nt][0] = __float_as_uint(Bs[c*GLDS + kc + tig]);
                bf[nt][1] = __float_as_uint(Bs[c*GLDS + kc + 4 + tig]);
            }
            #pragma unroll
            for (int mt = 0; mt < 4; mt++)
                #pragma unroll
                for (int nt = 0; nt < 4; nt++)
                    MMA_TF32(acc[mt][nt], af[mt], bf[nt]);
        }
        __syncthreads();
    }

    #pragma unroll
    for (int mt = 0; mt < 4; mt++) {
        const int r0 = n0 + wm * 64 + mt * 16 + g;
        #pragma unroll
        for (int nt = 0; nt < 4; nt++) {
            const int col = m0 + wn * 32 + nt * 8 + 2 * tig;
            float2 v0 = make_float2(acc[mt][nt][0], acc[mt][nt][1]);
            float2 v1 = make_float2(acc[mt][nt][2], acc[mt][nt][3]);
            if (EPI == 1 || EPI == 3) {
                float2 bb = *(const float2*)&bias[col];
                v0.x += bb.x; v0.y += bb.y;
                v1.x += bb.x; v1.y += bb.y;
            }
            if (EPI == 3) {
                v0.x = fmaxf(v0.x, 0.f); v0.y = fmaxf(v0.y, 0.f);
                v1.x = fmaxf(v1.x, 0.f); v1.y = fmaxf(v1.y, 0.f);
            }
            if (EPI == 2 || EPI == 3) {
                float2 r0v = *(const float2*)&res[(size_t)r0 * M + col];
                float2 r1v = *(const float2*)&res[(size_t)(r0 + 8) * M + col];
                v0.x += r0v.x; v0.y += r0v.y;
                v1.x += r1v.x; v1.y += r1v.y;
            }
            if (RND) {
                v0.x = rnd_tf32(v0.x); v0.y = rnd_tf32(v0.y);
                v1.x = rnd_tf32(v1.x); v1.y = rnd_tf32(v1.y);
            }
            *(float2*)&C[(size_t)r0 * M + col]       = v0;
            *(float2*)&C[(size_t)(r0 + 8) * M + col] = v1;
        }
    }
}

// ---------------- Tensor-core flash attention -------------------------------
// Q/K/V arrive pre-rounded tf32 from the QKV GEMM -> no operand cvt here.
#define AQS  0        // Qs [128][76]
#define AKS  9728     // Ks [2][64][76]
#define AVS  19456    // Vs [2][64][72]
#define APS  28672    // Ps [128][76]
#define AMSK 38400    // msk[2][64]
#define ASMEM_FLOATS 38528
#define ASMEM_BYTES  (ASMEM_FLOATS*4)

__global__ __launch_bounds__(256) void attn_tc(const float* __restrict__ Q,
                                               const float* __restrict__ K,
                                               const float* __restrict__ V,
                                               const unsigned char* __restrict__ mask,
                                               float* __restrict__ O)
{
    extern __shared__ float sh[];
    float* Qs  = sh + AQS;
    float* Ks  = sh + AKS;
    float* Vs  = sh + AVS;
    float* Ps  = sh + APS;
    float* msk = sh + AMSK;

    const int t    = threadIdx.x;
    const int lane = t & 31;
    const int warp = t >> 5;
    const int g    = lane >> 2;
    const int tig  = lane & 3;
    const int q0   = blockIdx.x * 128;
    const int h    = blockIdx.y;
    const int b    = blockIdx.z;
    const size_t base = (size_t)b * SEQ * D_MODEL + (size_t)h * DKH;
    const int rA = warp * 16 + g;

    #pragma unroll
    for (int i = 0; i < 8; i++) {
        int idx = t + i * 256, row = idx >> 4, c4 = (idx & 15) * 4;
        CP_ASYNC16(smem_u32(&Qs[row * 76 + c4]),
                   &Q[base + (size_t)(q0 + row) * D_MODEL + c4]);
    }
    #pragma unroll
    for (int i = 0; i < 4; i++) {
        int idx = t + i * 256, row = idx >> 4, c4 = (idx & 15) * 4;
        CP_ASYNC16(smem_u32(&Ks[row * 76 + c4]),
                   &K[base + (size_t)row * D_MODEL + c4]);
        CP_ASYNC16(smem_u32(&Vs[row * 72 + c4]),
                   &V[base + (size_t)row * D_MODEL + c4]);
    }
    if (t < 64) msk[t] = mask[(size_t)b * SEQ + t] ? -3.0e38f : 0.f;
    CP_COMMIT();

    float m0 = -3.0e38f, m1 = -3.0e38f, l0 = 0.f, l1 = 0.f;
    float oacc[8][4];
    #pragma unroll
    for (int nt = 0; nt < 8; nt++)
        #pragma unroll
        for (int c = 0; c < 4; c++) oacc[nt][c] = 0.f;

    const int ntiles = SEQ / 64;
    for (int kt = 0; kt < ntiles; kt++) {
        const int cur = kt & 1;
        CP_WAIT(0);
        __syncthreads();
        if (kt + 1 < ntiles) {
            const int nxt = cur ^ 1;
            const int k0n = (kt + 1) * 64;
            #pragma unroll
            for (int i = 0; i < 4; i++) {
                int idx = t + i * 256, row = idx >> 4, c4 = (idx & 15) * 4;
                CP_ASYNC16(smem_u32(&Ks[nxt * 4864 + row * 76 + c4]),
                           &K[base + (size_t)(k0n + row) * D_MODEL + c4]);
                CP_ASYNC16(smem_u32(&Vs[nxt * 4608 + row * 72 + c4]),
                           &V[base + (size_t)(k0n + row) * D_MODEL + c4]);
            }
            if (t < 64) msk[nxt * 64 + t] =
                mask[(size_t)b * SEQ + k0n + t] ? -3.0e38f : 0.f;
            CP_COMMIT();
        }
        const float* Kc = Ks + cur * 4864;
        const float* Vc = Vs + cur * 4608;
        const float* mc = msk + cur * 64;

        // ---- S = Q K^T ----
        float sc[8][4];
        #pragma unroll
        for (int nt = 0; nt < 8; nt++)
            #pragma unroll
            for (int c = 0; c < 4; c++) sc[nt][c] = 0.f;

        #pragma unroll
        for (int kc = 0; kc < 64; kc += 8) {
            uint32_t af[4];
            af[0] = __float_as_uint(Qs[rA * 76 + kc + tig]);
            af[1] = __float_as_uint(Qs[(rA + 8) * 76 + kc + tig]);
            af[2] = __float_as_uint(Qs[rA * 76 + kc + 4 + tig]);
            af[3] = __float_as_uint(Qs[(rA + 8) * 76 + kc + 4 + tig]);
            #pragma unroll
            for (int nt = 0; nt < 8; nt++) {
                uint32_t bf[2];
                bf[0] = __float_as_uint(Kc[(nt * 8 + g) * 76 + kc + tig]);
                bf[1] = __float_as_uint(Kc[(nt * 8 + g) * 76 + kc + 4 + tig]);
                MMA_TF32(sc[nt], af, bf);
            }
        }

        // ---- scale + mask + row stats ----
        float tm0 = -3.0e38f, tm1 = -3.0e38f;
        #pragma unroll
        for (int nt = 0; nt < 8; nt++) {
            const float mk0 = mc[nt * 8 + 2 * tig];
            const float mk1 = mc[nt * 8 + 2 * tig + 1];
            sc[nt][0] = sc[nt][0] * 0.125f + mk0;
            sc[nt][1] = sc[nt][1] * 0.125f + mk1;
            sc[nt][2] = sc[nt][2] * 0.125f + mk0;
            sc[nt][3] = sc[nt][3] * 0.125f + mk1;
            tm0 = fmaxf(tm0, fmaxf(sc[nt][0], sc[nt][1]));
            tm1 = fmaxf(tm1, fmaxf(sc[nt][2], sc[nt][3]));
        }
        tm0 = fmaxf(tm0, __shfl_xor_sync(0xffffffffu, tm0, 1));
        tm0 = fmaxf(tm0, __shfl_xor_sync(0xffffffffu, tm0, 2));
        tm1 = fmaxf(tm1, __shfl_xor_sync(0xffffffffu, tm1, 1));
        tm1 = fmaxf(tm1, __shfl_xor_sync(0xffffffffu, tm1, 2));

        const float nm0 = fmaxf(m0, tm0), nm1 = fmaxf(m1, tm1);
        const float a0 = __expf(m0 - nm0), a1 = __expf(m1 - nm1);

        float ps0 = 0.f, ps1 = 0.f;
        #pragma unroll
        for (int nt = 0; nt < 8; nt++) {
            const float p0 = __expf(sc[nt][0] - nm0);
            const float p1 = __expf(sc[nt][1] - nm0);
            const float p2 = __expf(sc[nt][2] - nm1);
            const float p3 = __expf(sc[nt][3] - nm1);
            ps0 += p0 + p1; ps1 += p2 + p3;
            *(float2*)&Ps[rA * 76 + nt * 8 + 2 * tig] =
                make_float2(rnd_tf32(p0), rnd_tf32(p1));
            *(float2*)&Ps[(rA + 8) * 76 + nt * 8 + 2 * tig] =
                make_float2(rnd_tf32(p2), rnd_tf32(p3));
        }
        ps0 += __shfl_xor_sync(0xffffffffu, ps0, 1);
        ps0 += __shfl_xor_sync(0xffffffffu, ps0, 2);
        ps1 += __shfl_xor_sync(0xffffffffu, ps1, 1);
        ps1 += __shfl_xor_sync(0xffffffffu, ps1, 2);

        l0 = l0 * a0 + ps0;  l1 = l1 * a1 + ps1;
        m0 = nm0;  m1 = nm1;
        #pragma unroll
        for (int nt = 0; nt < 8; nt++) {
            oacc[nt][0] *= a0; oacc[nt][1] *= a0;
            oacc[nt][2] *= a1; oacc[nt][3] *= a1;
        }
        __syncwarp();

        // ---- O += P V ----
        #pragma unroll
        for (int kc = 0; kc < 64; kc += 8) {
            uint32_t af[4];
            af[0] = __float_as_uint(Ps[rA * 76 + kc + tig]);
            af[1] = __float_as_uint(Ps[(rA + 8) * 76 + kc + tig]);
            af[2] = __float_as_uint(Ps[rA * 76 + kc + 4 + tig]);
            af[3] = __float_as_uint(Ps[(rA + 8) * 76 + kc + 4 + tig]);
            #pragma unroll
            for (int nt = 0; nt < 8; nt++) {
                uint32_t bf[2];
                bf[0] = __float_as_uint(Vc[(kc + tig) * 72 + nt * 8 + g]);
                bf[1] = __float_as_uint(Vc[(kc + 4 + tig) * 72 + nt * 8 + g]);
                MMA_TF32(oacc[nt], af, bf);
            }
        }
    }

    // ---- epilogue: normalize, round (feeds W_O GEMM), store ----
    const float i0 = 1.f / l0, i1 = 1.f / l1;
    #pragma unroll
    for (int nt = 0; nt < 8; nt++) {
        const int col = nt * 8 + 2 * tig;
        *(float2*)&O[base + (size_t)(q0 + rA) * D_MODEL + col] =
            make_float2(rnd_tf32(oacc[nt][0] * i0), rnd_tf32(oacc[nt][1] * i0));
        *(float2*)&O[base + (size_t)(q0 + rA + 8) * D_MODEL + col] =
            make_float2(rnd_tf32(oacc[nt][2] * i1), rnd_tf32(oacc[nt][3] * i1));
    }
}

// ---------------- launch ---------------------------------------------------
extern "C" void kernel_launch(void* const* d_in, const int* in_sizes, int n_in,
                              void* d_out, int out_size)
{
    const float* x     = (const float*)d_in[0];
    const unsigned char* mask = (const unsigned char*)d_in[1];
    const float* W_Q   = (const float*)d_in[2];
    const float* W_K   = (const float*)d_in[3];
    const float* W_V   = (const float*)d_in[4];
    const float* W_O   = (const float*)d_in[5];
    const float* W1    = (const float*)d_in[6];
    const float* b1    = (const float*)d_in[7];
    const float* W2    = (const float*)d_in[8];
    const float* b2    = (const float*)d_in[9];
    const float* g1    = (const float*)d_in[10];
    const float* beta1 = (const float*)d_in[11];
    const float* g2    = (const float*)d_in[12];
    const float* beta2 = (const float*)d_in[13];
    float* out = (float*)d_out;

    float *h1, *qm, *km, *vm, *at, *x1, *h2, *f1;
    float *wq, *wk, *wv, *wo, *w1, *w2;
    cudaGetSymbolAddress((void**)&h1, g_h1);
    cudaGetSymbolAddress((void**)&qm, g_q);
    cudaGetSymbolAddress((void**)&km, g_k);
    cudaGetSymbolAddress((void**)&vm, g_v);
    cudaGetSymbolAddress((void**)&at, g_at);
    cudaGetSymbolAddress((void**)&x1, g_x1);
    cudaGetSymbolAddress((void**)&h2, g_h2);
    cudaGetSymbolAddress((void**)&f1, g_f1);
    cudaGetSymbolAddress((void**)&wq, g_wq);
    cudaGetSymbolAddress((void**)&wk, g_wk);
    cudaGetSymbolAddress((void**)&wv, g_wv);
    cudaGetSymbolAddress((void**)&wo, g_wo);
    cudaGetSymbolAddress((void**)&w1, g_w1);
    cudaGetSymbolAddress((void**)&w2, g_w2);

    cudaFuncSetAttribute(attn_tc, cudaFuncAttributeMaxDynamicSharedMemorySize,
                         ASMEM_BYTES);
    cudaFuncSetAttribute(gemm_tf32<0,1>, cudaFuncAttributeMaxDynamicSharedMemorySize, GSMEM_BYTES);
    cudaFuncSetAttribute(gemm_tf32<2,0>, cudaFuncAttributeMaxDynamicSharedMemorySize, GSMEM_BYTES);
    cudaFuncSetAttribute(gemm_tf32<1,1>, cudaFuncAttributeMaxDynamicSharedMemorySize, GSMEM_BYTES);
    cudaFuncSetAttribute(gemm_tf32<3,0>, cudaFuncAttributeMaxDynamicSharedMemorySize, GSMEM_BYTES);

    const dim3 gDD(D_MODEL/128, NTOK/128);   // (8, 32)
    const dim3 gDF(D_FF/128,    NTOK/128);   // (32, 32)
    const int DD4 = D_MODEL*D_MODEL/4, DF4 = D_FF*D_MODEL/4;

    // 0. pre-round weights into scratch (tf32)
    round_copy<<<(DD4+255)/256, 256>>>((const float4*)W_Q, (float4*)wq, DD4);
    round_copy<<<(DD4+255)/256, 256>>>((const float4*)W_K, (float4*)wk, DD4);
    round_copy<<<(DD4+255)/256, 256>>>((const float4*)W_V, (float4*)wv, DD4);
    round_copy<<<(DD4+255)/256, 256>>>((const float4*)W_O, (float4*)wo, DD4);
    round_copy<<<(DF4+255)/256, 256>>>((const float4*)W1,  (float4*)w1, DF4);
    round_copy<<<(DF4+255)/256, 256>>>((const float4*)W2,  (float4*)w2, DF4);

    // 1. pre-LN (rounded output)
    ln_kernel<<<NTOK, 256>>>(x, g1, beta1, h1);
    // 2. QKV projections (rounded outputs feed attention)
    gemm_tf32<0,1><<<gDD, 256, GSMEM_BYTES>>>(h1, wq, qm, NTOK, D_MODEL, D_MODEL, nullptr, nullptr);
    gemm_tf32<0,1><<<gDD, 256, GSMEM_BYTES>>>(h1, wk, km, NTOK, D_MODEL, D_MODEL, nullptr, nullptr);
    gemm_tf32<0,1><<<gDD, 256, GSMEM_BYTES>>>(h1, wv, vm, NTOK, D_MODEL, D_MODEL, nullptr, nullptr);
    // 3. tensor-core flash attention (rounded output feeds W_O GEMM)
    attn_tc<<<dim3(SEQ/128, HEADS, BATCH), 256, ASMEM_BYTES>>>(qm, km, vm, mask, at);
    // 4. output projection + residual (exact fp32 out: residual path)
    gemm_tf32<2,0><<<gDD, 256, GSMEM_BYTES>>>(at, wo, x1, NTOK, D_MODEL, D_MODEL, nullptr, x);
    // 5. second LN (rounded output)
    ln_kernel<<<NTOK, 256>>>(x1, g2, beta2, h2);
    // 6. FFN1 (+b1, rounded output feeds FFN2)
    gemm_tf32<1,1><<<gDF, 256, GSMEM_BYTES>>>(h2, w1, f1, NTOK, D_FF, D_MODEL, b1, nullptr);
    // 7. FFN2: relu(C + b2) + residual(x1), exact fp32 final output
    gemm_tf32<3,0><<<gDD, 256, GSMEM_BYTES>>>(f1, w2, out, NTOK, D_MODEL, D_FF, b2, x1);
}

// round 6
// speedup vs baseline: 1.7723x; 1.7723x over previous
#include <cuda_runtime.h>
#include <cuda_fp16.h>
#include <cstdint>
#include <cstddef>

#define D_MODEL 1024
#define D_FF    4096
#define HEADS   16
#define DKH     64
#define BATCH   2
#define SEQ     2048
#define NTOK    (BATCH*SEQ)

// ---------------- scratch (device globals; no allocations allowed) ----------
__device__ __half g_h1[NTOK * D_MODEL];
__device__ __half g_q [NTOK * D_MODEL];
__device__ __half g_k [NTOK * D_MODEL];
__device__ __half g_v [NTOK * D_MODEL];
__device__ __half g_at[NTOK * D_MODEL];
__device__ float  g_x1[NTOK * D_MODEL];
__device__ __half g_h2[NTOK * D_MODEL];
__device__ __half g_f1[NTOK * D_FF];
// fp16 weight copies
__device__ __half g_wq[D_MODEL * D_MODEL];
__device__ __half g_wk[D_MODEL * D_MODEL];
__device__ __half g_wv[D_MODEL * D_MODEL];
__device__ __half g_wo[D_MODEL * D_MODEL];
__device__ __half g_w1[D_FF * D_MODEL];
__device__ __half g_w2[D_MODEL * D_FF];

// ---------------- helpers ---------------------------------------------------
__device__ __forceinline__ uint32_t smem_u32(const void* p) {
    return (uint32_t)__cvta_generic_to_shared(p);
}
#define CP_ASYNC16(dst, src) \
    asm volatile("cp.async.cg.shared.global [%0], [%1], 16;\n" :: "r"(dst), "l"(src))
#define CP_COMMIT() asm volatile("cp.async.commit_group;\n" ::: "memory")
#define CP_WAIT(n)  asm volatile("cp.async.wait_group %0;\n" :: "n"(n) : "memory")

#define MMA_F16(d, a, b) \
    asm volatile("mma.sync.aligned.m16n8k16.row.col.f32.f16.f16.f32 " \
                 "{%0,%1,%2,%3},{%4,%5,%6,%7},{%8,%9},{%0,%1,%2,%3};" \
                 : "+f"(d[0]), "+f"(d[1]), "+f"(d[2]), "+f"(d[3]) \
                 : "r"(a[0]), "r"(a[1]), "r"(a[2]), "r"(a[3]), \
                   "r"(b[0]), "r"(b[1]))

#define LDMX4_TRANS(r0, r1, r2, r3, addr) \
    asm volatile("ldmatrix.sync.aligned.m8n8.x4.trans.shared.b16 {%0,%1,%2,%3}, [%4];" \
                 : "=r"(r0), "=r"(r1), "=r"(r2), "=r"(r3) : "r"(addr))

__device__ __forceinline__ uint32_t h2u(__half2 h) {
    return *reinterpret_cast<uint32_t*>(&h);
}

// ---------------- weights: fp32 -> fp16 copy --------------------------------
__global__ __launch_bounds__(256) void conv_half(const float4* __restrict__ in,
                                                 __half* __restrict__ out, int n4)
{
    int i = blockIdx.x * 256 + threadIdx.x;
    if (i < n4) {
        float4 v = in[i];
        __half2* o = (__half2*)(out + (size_t)i * 4);
        o[0] = __floats2half2_rn(v.x, v.y);
        o[1] = __floats2half2_rn(v.z, v.w);
    }
}

// ---------------- LayerNorm (fp32 in, fp16 out) -----------------------------
__global__ __launch_bounds__(256) void ln_kernel(const float* __restrict__ x,
                                                 const float* __restrict__ g,
                                                 const float* __restrict__ b,
                                                 __half* __restrict__ out)
{
    __shared__ float red[8];
    __shared__ float bcast;
    const int row = blockIdx.x;
    const int t = threadIdx.x;
    const int lane = t & 31, w = t >> 5;

    const float4* x4 = (const float4*)x + (size_t)row * 256;
    float4 v = x4[t];

    float s = v.x + v.y + v.z + v.w;
    #pragma unroll
    for (int o = 16; o; o >>= 1) s += __shfl_xor_sync(0xffffffffu, s, o);
    if (lane == 0) red[w] = s;
    __syncthreads();
    if (t == 0) {
        float tot = 0.f;
        #pragma unroll
        for (int i = 0; i < 8; i++) tot += red[i];
        bcast = tot * (1.f / 1024.f);
    }
    __syncthreads();
    const float mu = bcast;

    float4 d = make_float4(v.x - mu, v.y - mu, v.z - mu, v.w - mu);
    float vs = d.x*d.x + d.y*d.y + d.z*d.z + d.w*d.w;
    __syncthreads();
    #pragma unroll
    for (int o = 16; o; o >>= 1) vs += __shfl_xor_sync(0xffffffffu, vs, o);
    if (lane == 0) red[w] = vs;
    __syncthreads();
    if (t == 0) {
        float tot = 0.f;
        #pragma unroll
        for (int i = 0; i < 8; i++) tot += red[i];
        bcast = rsqrtf(tot * (1.f / 1024.f) + 1e-5f);
    }
    __syncthreads();
    const float rs = bcast;

    float4 gv = ((const float4*)g)[t];
    float4 bv = ((const float4*)b)[t];
    __half2* orow = (__half2*)(out + (size_t)row * 1024);
    orow[t*2]   = __floats2half2_rn(d.x*rs*gv.x + bv.x, d.y*rs*gv.y + bv.y);
    orow[t*2+1] = __floats2half2_rn(d.z*rs*gv.z + bv.z, d.w*rs*gv.w + bv.w);
}

// ---------------- FP16 tensor-core GEMM NT ----------------------------------
// C[N,M] = A[N,K] * B[M,K]^T, A/B fp16, accum fp32.  128x128 tile, BK=32,
// 256 thr, 2x4 warps, 64x32/warp via 4x4 m16n8k16.  cp.async double-buffered.
// EPI: 0=none, 1=+bias, 2=+res, 3=relu(+bias)+res.  HOUT: 1 = store half.
#define GLDSH 40   // 32 + 8 pad (halves); 80B rows -> conflict-free frags

template<int EPI, int HOUT>
__global__ __launch_bounds__(256) void gemm_f16(const __half* __restrict__ A,
                                                const __half* __restrict__ B,
                                                void* __restrict__ Cv,
                                                int N, int M, int K,
                                                const float* __restrict__ bias,
                                                const float* __restrict__ res)
{
    __shared__ __half As[2][128][GLDSH];
    __shared__ __half Bs[2][128][GLDSH];

    const int t    = threadIdx.x;
    const int lane = t & 31;
    const int warp = t >> 5;
    const int wm   = warp >> 2;
    const int wn   = warp & 3;
    const int g    = lane >> 2;
    const int tig  = lane & 3;
    const int n0   = blockIdx.y * 128;
    const int m0   = blockIdx.x * 128;

    const int lr = t >> 1;             // 0..127
    const int sg = (t & 1) * 16;       // 0 or 16 (halves)

    const __half* Ar = A + (size_t)(n0 + lr) * K + sg;
    const __half* Br = B + (size_t)(m0 + lr) * K + sg;

    float acc[4][4][4];
    #pragma unroll
    for (int i = 0; i < 4; i++)
        #pragma unroll
        for (int j = 0; j < 4; j++)
            #pragma unroll
            for (int c = 0; c < 4; c++) acc[i][j][c] = 0.f;

    const int nK = K / 32;

    {
        CP_ASYNC16(smem_u32(&As[0][lr][sg]),     Ar);
        CP_ASYNC16(smem_u32(&As[0][lr][sg + 8]), Ar + 8);
        CP_ASYNC16(smem_u32(&Bs[0][lr][sg]),     Br);
        CP_ASYNC16(smem_u32(&Bs[0][lr][sg + 8]), Br + 8);
        CP_COMMIT();
    }

    for (int kt = 0; kt < nK; kt++) {
        const int cur = kt & 1;
        if (kt + 1 < nK) {
            const int nxt = cur ^ 1;
            const int ko = (kt + 1) * 32;
            CP_ASYNC16(smem_u32(&As[nxt][lr][sg]),     Ar + ko);
            CP_ASYNC16(smem_u32(&As[nxt][lr][sg + 8]), Ar + ko + 8);
            CP_ASYNC16(smem_u32(&Bs[nxt][lr][sg]),     Br + ko);
            CP_ASYNC16(smem_u32(&Bs[nxt][lr][sg + 8]), Br + ko + 8);
            CP_COMMIT();
            CP_WAIT(1);
        } else {
            CP_WAIT(0);
        }
        __syncthreads();

        #pragma unroll
        for (int ks = 0; ks < 2; ks++) {
            const int kc = ks * 16;
            uint32_t af[4][4];
            #pragma unroll
            for (int mt = 0; mt < 4; mt++) {
                const int r = wm * 64 + mt * 16 + g;
                af[mt][0] = *(const uint32_t*)&As[cur][r    ][kc + 2*tig];
                af[mt][1] = *(const uint32_t*)&As[cur][r + 8][kc + 2*tig];
                af[mt][2] = *(const uint32_t*)&As[cur][r    ][kc + 8 + 2*tig];
                af[mt][3] = *(const uint32_t*)&As[cur][r + 8][kc + 8 + 2*tig];
            }
            uint32_t bf[4][2];
            #pragma unroll
            for (int nt = 0; nt < 4; nt++) {
                const int c = wn * 32 + nt * 8 + g;
                bf[nt][0] = *(const uint32_t*)&Bs[cur][c][kc + 2*tig];
                bf[nt][1] = *(const uint32_t*)&Bs[cur][c][kc + 8 + 2*tig];
            }
            #pragma unroll
            for (int mt = 0; mt < 4; mt++)
                #pragma unroll
                for (int nt = 0; nt < 4; nt++)
                    MMA_F16(acc[mt][nt], af[mt], bf[nt]);
        }
        __syncthreads();
    }

    #pragma unroll
    for (int mt = 0; mt < 4; mt++) {
        const int r0 = n0 + wm * 64 + mt * 16 + g;
        #pragma unroll
        for (int nt = 0; nt < 4; nt++) {
            const int col = m0 + wn * 32 + nt * 8 + 2 * tig;
            float2 v0 = make_float2(acc[mt][nt][0], acc[mt][nt][1]);
            float2 v1 = make_float2(acc[mt][nt][2], acc[mt][nt][3]);
            if (EPI == 1 || EPI == 3) {
                float2 bb = *(const float2*)&bias[col];
                v0.x += bb.x; v0.y += bb.y;
                v1.x += bb.x; v1.y += bb.y;
            }
            if (EPI == 3) {
                v0.x = fmaxf(v0.x, 0.f); v0.y = fmaxf(v0.y, 0.f);
                v1.x = fmaxf(v1.x, 0.f); v1.y = fmaxf(v1.y, 0.f);
            }
            if (EPI == 2 || EPI == 3) {
                float2 r0v = *(const float2*)&res[(size_t)r0 * M + col];
                float2 r1v = *(const float2*)&res[(size_t)(r0 + 8) * M + col];
                v0.x += r0v.x; v0.y += r0v.y;
                v1.x += r1v.x; v1.y += r1v.y;
            }
            if (HOUT) {
                __half* C = (__half*)Cv;
                *(__half2*)&C[(size_t)r0 * M + col]       = __floats2half2_rn(v0.x, v0.y);
                *(__half2*)&C[(size_t)(r0 + 8) * M + col] = __floats2half2_rn(v1.x, v1.y);
            } else {
                float* C = (float*)Cv;
                *(float2*)&C[(size_t)r0 * M + col]       = v0;
                *(float2*)&C[(size_t)(r0 + 8) * M + col] = v1;
            }
        }
    }
}

// ---------------- FP16 tensor-core flash attention ---------------------------
// 128 queries/CTA x 64-key tiles, dk=64.  8 warps x 16 query rows.
// S and PV via m16n8k16 fp16 mma (fp32 accum).  V frags via ldmatrix.trans.
// smem halves: Qs[128][72], Ks[2][64][72], Vs[2][64][72], Ps[128][72]; msk fp32
#define HQS  0
#define HKS  9216
#define HVS  18432
#define HPS  27648
#define HTOT 36864                       // halves
#define AMSK_B (HTOT*2)                  // byte offset of fp32 mask[2][64]
#define ASMEM_BYTES (AMSK_B + 2*64*4)
#define KSTG 4608                        // 64*72 halves per stage

__global__ __launch_bounds__(256) void attn_tc(const __half* __restrict__ Q,
                                               const __half* __restrict__ K,
                                               const __half* __restrict__ V,
                                               const unsigned char* __restrict__ mask,
                                               __half* __restrict__ O)
{
    extern __shared__ char shb[];
    __half* Qs  = (__half*)shb + HQS;
    __half* Ks  = (__half*)shb + HKS;
    __half* Vs  = (__half*)shb + HVS;
    __half* Ps  = (__half*)shb + HPS;
    float*  msk = (float*)(shb + AMSK_B);

    const int t    = threadIdx.x;
    const int lane = t & 31;
    const int warp = t >> 5;
    const int g    = lane >> 2;
    const int tig  = lane & 3;
    const int q0   = blockIdx.x * 128;
    const int h    = blockIdx.y;
    const int b    = blockIdx.z;
    const size_t base = (size_t)b * SEQ * D_MODEL + (size_t)h * DKH;
    const int rA = warp * 16 + g;

    // prologue: Q (128x64 halves) + K/V tile 0 + mask
    #pragma unroll
    for (int i = 0; i < 4; i++) {
        int idx = t + i * 256, row = idx >> 3, s8 = (idx & 7) * 8;
        CP_ASYNC16(smem_u32(&Qs[row * 72 + s8]),
                   &Q[base + (size_t)(q0 + row) * D_MODEL + s8]);
    }
    #pragma unroll
    for (int i = 0; i < 2; i++) {
        int idx = t + i * 256, row = idx >> 3, s8 = (idx & 7) * 8;
        CP_ASYNC16(smem_u32(&Ks[row * 72 + s8]),
                   &K[base + (size_t)row * D_MODEL + s8]);
        CP_ASYNC16(smem_u32(&Vs[row * 72 + s8]),
                   &V[base + (size_t)row * D_MODEL + s8]);
    }
    if (t < 64) msk[t] = mask[(size_t)b * SEQ + t] ? -3.0e38f : 0.f;
    CP_COMMIT();

    float m0 = -3.0e38f, m1 = -3.0e38f, l0 = 0.f, l1 = 0.f;
    float oacc[8][4];
    #pragma unroll
    for (int nt = 0; nt < 8; nt++)
        #pragma unroll
        for (int c = 0; c < 4; c++) oacc[nt][c] = 0.f;

    const int ntiles = SEQ / 64;
    for (int kt = 0; kt < ntiles; kt++) {
        const int cur = kt & 1;
        CP_WAIT(0);
        __syncthreads();
        if (kt + 1 < ntiles) {
            const int nxt = cur ^ 1;
            const int k0n = (kt + 1) * 64;
            #pragma unroll
            for (int i = 0; i < 2; i++) {
                int idx = t + i * 256, row = idx >> 3, s8 = (idx & 7) * 8;
                CP_ASYNC16(smem_u32(&Ks[nxt * KSTG + row * 72 + s8]),
                           &K[base + (size_t)(k0n + row) * D_MODEL + s8]);
                CP_ASYNC16(smem_u32(&Vs[nxt * KSTG + row * 72 + s8]),
                           &V[base + (size_t)(k0n + row) * D_MODEL + s8]);
            }
            if (t < 64) msk[nxt * 64 + t] =
                mask[(size_t)b * SEQ + k0n + t] ? -3.0e38f : 0.f;
            CP_COMMIT();
        }
        const __half* Kc = Ks + cur * KSTG;
        const __half* Vc = Vs + cur * KSTG;
        const float*  mc = msk + cur * 64;

        // ---- S = Q K^T  (16 rows x 64 keys per warp), dk=64 = 4 k16 steps ----
        float sc[8][4];
        #pragma unroll
        for (int nt = 0; nt < 8; nt++)
            #pragma unroll
            for (int c = 0; c < 4; c++) sc[nt][c] = 0.f;

        #pragma unroll
        for (int kc = 0; kc < 64; kc += 16) {
            uint32_t af[4];
            af[0] = *(const uint32_t*)&Qs[rA * 72 + kc + 2*tig];
            af[1] = *(const uint32_t*)&Qs[(rA + 8) * 72 + kc + 2*tig];
            af[2] = *(const uint32_t*)&Qs[rA * 72 + kc + 8 + 2*tig];
            af[3] = *(const uint32_t*)&Qs[(rA + 8) * 72 + kc + 8 + 2*tig];
            #pragma unroll
            for (int nt = 0; nt < 8; nt++) {
                const int c = nt * 8 + g;
                uint32_t bf[2];
                bf[0] = *(const uint32_t*)&Kc[c * 72 + kc + 2*tig];
                bf[1] = *(const uint32_t*)&Kc[c * 72 + kc + 8 + 2*tig];
                MMA_F16(sc[nt], af, bf);
            }
        }

        // ---- scale + mask + row stats ----
        float tm0 = -3.0e38f, tm1 = -3.0e38f;
        #pragma unroll
        for (int nt = 0; nt < 8; nt++) {
            const float mk0 = mc[nt * 8 + 2 * tig];
            const float mk1 = mc[nt * 8 + 2 * tig + 1];
            sc[nt][0] = sc[nt][0] * 0.125f + mk0;
            sc[nt][1] = sc[nt][1] * 0.125f + mk1;
            sc[nt][2] = sc[nt][2] * 0.125f + mk0;
            sc[nt][3] = sc[nt][3] * 0.125f + mk1;
            tm0 = fmaxf(tm0, fmaxf(sc[nt][0], sc[nt][1]));
            tm1 = fmaxf(tm1, fmaxf(sc[nt][2], sc[nt][3]));
        }
        tm0 = fmaxf(tm0, __shfl_xor_sync(0xffffffffu, tm0, 1));
        tm0 = fmaxf(tm0, __shfl_xor_sync(0xffffffffu, tm0, 2));
        tm1 = fmaxf(tm1, __shfl_xor_sync(0xffffffffu, tm1, 1));
        tm1 = fmaxf(tm1, __shfl_xor_sync(0xffffffffu, tm1, 2));

        const float nm0 = fmaxf(m0, tm0), nm1 = fmaxf(m1, tm1);
        const float a0 = __expf(m0 - nm0), a1 = __expf(m1 - nm1);

        float ps0 = 0.f, ps1 = 0.f;
        #pragma unroll
        for (int nt = 0; nt < 8; nt++) {
            const float p0 = __expf(sc[nt][0] - nm0);
            const float p1 = __expf(sc[nt][1] - nm0);
            const float p2 = __expf(sc[nt][2] - nm1);
            const float p3 = __expf(sc[nt][3] - nm1);
            ps0 += p0 + p1; ps1 += p2 + p3;
            *(__half2*)&Ps[rA * 72 + nt * 8 + 2*tig]       = __floats2half2_rn(p0, p1);
            *(__half2*)&Ps[(rA + 8) * 72 + nt * 8 + 2*tig] = __floats2half2_rn(p2, p3);
        }
        ps0 += __shfl_xor_sync(0xffffffffu, ps0, 1);
        ps0 += __shfl_xor_sync(0xffffffffu, ps0, 2);
        ps1 += __shfl_xor_sync(0xffffffffu, ps1, 1);
        ps1 += __shfl_xor_sync(0xffffffffu, ps1, 2);

        l0 = l0 * a0 + ps0;  l1 = l1 * a1 + ps1;
        m0 = nm0;  m1 = nm1;
        #pragma unroll
        for (int nt = 0; nt < 8; nt++) {
            oacc[nt][0] *= a0; oacc[nt][1] *= a0;
            oacc[nt][2] *= a1; oacc[nt][3] *= a1;
        }
        __syncwarp();

        // ---- O += P V :  A = Ps rows (this warp), B = V via ldmatrix.trans --
        const int mi = lane >> 3, rr = lane & 7;   // ldmatrix lane mapping
        #pragma unroll
        for (int kc = 0; kc < 64; kc += 16) {
            uint32_t af[4];
            af[0] = *(const uint32_t*)&Ps[rA * 72 + kc + 2*tig];
            af[1] = *(const uint32_t*)&Ps[(rA + 8) * 72 + kc + 2*tig];
            af[2] = *(const uint32_t*)&Ps[rA * 72 + kc + 8 + 2*tig];
            af[3] = *(const uint32_t*)&Ps[(rA + 8) * 72 + kc + 8 + 2*tig];
            #pragma unroll
            for (int ntp = 0; ntp < 4; ntp++) {
                const int key = kc + ((mi & 1) << 3) + rr;
                const int dim = ntp * 16 + ((mi >> 1) << 3);
                uint32_t r0, r1, r2, r3;
                LDMX4_TRANS(r0, r1, r2, r3, smem_u32(&Vc[key * 72 + dim]));
                uint32_t b0[2] = {r0, r1};
                uint32_t b1[2] = {r2, r3};
                MMA_F16(oacc[2*ntp],     af, b0);
                MMA_F16(oacc[2*ntp + 1], af, b1);
            }
        }
    }

    // ---- epilogue: normalize, store half (feeds W_O GEMM) ----
    const float i0 = 1.f / l0, i1 = 1.f / l1;
    #pragma unroll
    for (int nt = 0; nt < 8; nt++) {
        const int col = nt * 8 + 2 * tig;
        *(__half2*)&O[base + (size_t)(q0 + rA) * D_MODEL + col] =
            __floats2half2_rn(oacc[nt][0] * i0, oacc[nt][1] * i0);
        *(__half2*)&O[base + (size_t)(q0 + rA + 8) * D_MODEL + col] =
            __floats2half2_rn(oacc[nt][2] * i1, oacc[nt][3] * i1);
    }
}

// ---------------- launch ---------------------------------------------------
extern "C" void kernel_launch(void* const* d_in, const int* in_sizes, int n_in,
                              void* d_out, int out_size)
{
    const float* x     = (const float*)d_in[0];
    const unsigned char* mask = (const unsigned char*)d_in[1];
    const float* W_Q   = (const float*)d_in[2];
    const float* W_K   = (const float*)d_in[3];
    const float* W_V   = (const float*)d_in[4];
    const float* W_O   = (const float*)d_in[5];
    const float* W1    = (const float*)d_in[6];
    const float* b1    = (const float*)d_in[7];
    const float* W2    = (const float*)d_in[8];
    const float* b2    = (const float*)d_in[9];
    const float* g1    = (const float*)d_in[10];
    const float* beta1 = (const float*)d_in[11];
    const float* g2    = (const float*)d_in[12];
    const float* beta2 = (const float*)d_in[13];
    float* out = (float*)d_out;

    __half *h1, *qm, *km, *vm, *at, *h2, *f1;
    __half *wq, *wk, *wv, *wo, *w1, *w2;
    float *x1;
    cudaGetSymbolAddress((void**)&h1, g_h1);
    cudaGetSymbolAddress((void**)&qm, g_q);
    cudaGetSymbolAddress((void**)&km, g_k);
    cudaGetSymbolAddress((void**)&vm, g_v);
    cudaGetSymbolAddress((void**)&at, g_at);
    cudaGetSymbolAddress((void**)&x1, g_x1);
    cudaGetSymbolAddress((void**)&h2, g_h2);
    cudaGetSymbolAddress((void**)&f1, g_f1);
    cudaGetSymbolAddress((void**)&wq, g_wq);
    cudaGetSymbolAddress((void**)&wk, g_wk);
    cudaGetSymbolAddress((void**)&wv, g_wv);
    cudaGetSymbolAddress((void**)&wo, g_wo);
    cudaGetSymbolAddress((void**)&w1, g_w1);
    cudaGetSymbolAddress((void**)&w2, g_w2);

    cudaFuncSetAttribute(attn_tc, cudaFuncAttributeMaxDynamicSharedMemorySize,
                         ASMEM_BYTES);

    const dim3 gDD(D_MODEL/128, NTOK/128);   // (8, 32)
    const dim3 gDF(D_FF/128,    NTOK/128);   // (32, 32)
    const int DD4 = D_MODEL*D_MODEL/4, DF4 = D_FF*D_MODEL/4;

    // 0. weights -> fp16 (once per launch)
    conv_half<<<(DD4+255)/256, 256>>>((const float4*)W_Q, wq, DD4);
    conv_half<<<(DD4+255)/256, 256>>>((const float4*)W_K, wk, DD4);
    conv_half<<<(DD4+255)/256, 256>>>((const float4*)W_V, wv, DD4);
    conv_half<<<(DD4+255)/256, 256>>>((const float4*)W_O, wo, DD4);
    conv_half<<<(DF4+255)/256, 256>>>((const float4*)W1,  w1, DF4);
    conv_half<<<(DF4+255)/256, 256>>>((const float4*)W2,  w2, DF4);

    // 1. pre-LN (fp16 out)
    ln_kernel<<<NTOK, 256>>>(x, g1, beta1, h1);
    // 2. QKV projections (fp16 out)
    gemm_f16<0,1><<<gDD, 256>>>(h1, wq, qm, NTOK, D_MODEL, D_MODEL, nullptr, nullptr);
    gemm_f16<0,1><<<gDD, 256>>>(h1, wk, km, NTOK, D_MODEL, D_MODEL, nullptr, nullptr);
    gemm_f16<0,1><<<gDD, 256>>>(h1, wv, vm, NTOK, D_MODEL, D_MODEL, nullptr, nullptr);
    // 3. fp16 tensor-core flash attention (fp16 out)
    attn_tc<<<dim3(SEQ/128, HEADS, BATCH), 256, ASMEM_BYTES>>>(qm, km, vm, mask, at);
    // 4. output projection + residual (fp32 out)
    gemm_f16<2,0><<<gDD, 256>>>(at, wo, x1, NTOK, D_MODEL, D_MODEL, nullptr, x);
    // 5. second LN (fp16 out)
    ln_kernel<<<NTOK, 256>>>(x1, g2, beta2, h2);
    // 6. FFN1 (+b1, fp16 out)
    gemm_f16<1,1><<<gDF, 256>>>(h2, w1, f1, NTOK, D_FF, D_MODEL, b1, nullptr);
    // 7. FFN2: relu(C + b2) + residual(x1), fp32 final
    gemm_f16<3,0><<<gDD, 256>>>(f1, w2, out, NTOK, D_MODEL, D_FF, b2, x1);
}

// round 7
// speedup vs baseline: 1.9038x; 1.0742x over previous
#include <cuda_runtime.h>
#include <cuda_fp16.h>
#include <cstdint>
#include <cstddef>

#define D_MODEL 1024
#define D_FF    4096
#define HEADS   16
#define DKH     64
#define BATCH   2
#define SEQ     2048
#define NTOK    (BATCH*SEQ)
#define D3      (3*D_MODEL)

// ---------------- scratch (device globals; no allocations allowed) ----------
__device__ __half g_h1 [NTOK * D_MODEL];
__device__ __half g_qkv[NTOK * D3];          // fused Q|K|V, row stride 3072
__device__ __half g_at [NTOK * D_MODEL];
__device__ float  g_x1 [NTOK * D_MODEL];
__device__ __half g_h2 [NTOK * D_MODEL];
__device__ __half g_f1 [NTOK * D_FF];
// fp16 weight copies
__device__ __half g_wqkv[D3 * D_MODEL];      // W_Q rows 0-1023 | W_K | W_V
__device__ __half g_wo[D_MODEL * D_MODEL];
__device__ __half g_w1[D_FF * D_MODEL];
__device__ __half g_w2[D_MODEL * D_FF];

// ---------------- helpers ---------------------------------------------------
__device__ __forceinline__ uint32_t smem_u32(const void* p) {
    return (uint32_t)__cvta_generic_to_shared(p);
}
#define CP_ASYNC16(dst, src) \
    asm volatile("cp.async.cg.shared.global [%0], [%1], 16;\n" :: "r"(dst), "l"(src))
#define CP_COMMIT() asm volatile("cp.async.commit_group;\n" ::: "memory")
#define CP_WAIT(n)  asm volatile("cp.async.wait_group %0;\n" :: "n"(n) : "memory")

#define MMA_F16(d, a, b) \
    asm volatile("mma.sync.aligned.m16n8k16.row.col.f32.f16.f16.f32 " \
                 "{%0,%1,%2,%3},{%4,%5,%6,%7},{%8,%9},{%0,%1,%2,%3};" \
                 : "+f"(d[0]), "+f"(d[1]), "+f"(d[2]), "+f"(d[3]) \
                 : "r"(a[0]), "r"(a[1]), "r"(a[2]), "r"(a[3]), \
                   "r"(b[0]), "r"(b[1]))

#define LDMX4(r0, r1, r2, r3, addr) \
    asm volatile("ldmatrix.sync.aligned.m8n8.x4.shared.b16 {%0,%1,%2,%3}, [%4];" \
                 : "=r"(r0), "=r"(r1), "=r"(r2), "=r"(r3) : "r"(addr))
#define LDMX4_TRANS(r0, r1, r2, r3, addr) \
    asm volatile("ldmatrix.sync.aligned.m8n8.x4.trans.shared.b16 {%0,%1,%2,%3}, [%4];" \
                 : "=r"(r0), "=r"(r1), "=r"(r2), "=r"(r3) : "r"(addr))

// ---------------- weight conversion -----------------------------------------
__global__ __launch_bounds__(256) void conv_half(const float4* __restrict__ in,
                                                 __half* __restrict__ out, int n4)
{
    int i = blockIdx.x * 256 + threadIdx.x;
    if (i < n4) {
        float4 v = in[i];
        __half2* o = (__half2*)(out + (size_t)i * 4);
        o[0] = __floats2half2_rn(v.x, v.y);
        o[1] = __floats2half2_rn(v.z, v.w);
    }
}

__global__ __launch_bounds__(256) void conv_qkv(const float4* __restrict__ q,
                                                const float4* __restrict__ k,
                                                const float4* __restrict__ v,
                                                __half* __restrict__ out)
{
    const int per = D_MODEL * D_MODEL / 4;     // float4 per matrix
    int i = blockIdx.x * 256 + threadIdx.x;    // < 3*per
    float4 val;
    if (i < per)            val = q[i];
    else if (i < 2 * per)   val = k[i - per];
    else                    val = v[i - 2 * per];
    __half2* o = (__half2*)(out + (size_t)i * 4);
    o[0] = __floats2half2_rn(val.x, val.y);
    o[1] = __floats2half2_rn(val.z, val.w);
}

// ---------------- LayerNorm (fp32 in, fp16 out) -----------------------------
__global__ __launch_bounds__(256) void ln_kernel(const float* __restrict__ x,
                                                 const float* __restrict__ g,
                                                 const float* __restrict__ b,
                                                 __half* __restrict__ out)
{
    __shared__ float red[8];
    __shared__ float bcast;
    const int row = blockIdx.x;
    const int t = threadIdx.x;
    const int lane = t & 31, w = t >> 5;

    const float4* x4 = (const float4*)x + (size_t)row * 256;
    float4 v = x4[t];

    float s = v.x + v.y + v.z + v.w;
    #pragma unroll
    for (int o = 16; o; o >>= 1) s += __shfl_xor_sync(0xffffffffu, s, o);
    if (lane == 0) red[w] = s;
    __syncthreads();
    if (t == 0) {
        float tot = 0.f;
        #pragma unroll
        for (int i = 0; i < 8; i++) tot += red[i];
        bcast = tot * (1.f / 1024.f);
    }
    __syncthreads();
    const float mu = bcast;

    float4 d = make_float4(v.x - mu, v.y - mu, v.z - mu, v.w - mu);
    float vs = d.x*d.x + d.y*d.y + d.z*d.z + d.w*d.w;
    __syncthreads();
    #pragma unroll
    for (int o = 16; o; o >>= 1) vs += __shfl_xor_sync(0xffffffffu, vs, o);
    if (lane == 0) red[w] = vs;
    __syncthreads();
    if (t == 0) {
        float tot = 0.f;
        #pragma unroll
        for (int i = 0; i < 8; i++) tot += red[i];
        bcast = rsqrtf(tot * (1.f / 1024.f) + 1e-5f);
    }
    __syncthreads();
    const float rs = bcast;

    float4 gv = ((const float4*)g)[t];
    float4 bv = ((const float4*)b)[t];
    __half2* orow = (__half2*)(out + (size_t)row * 1024);
    orow[t*2]   = __floats2half2_rn(d.x*rs*gv.x + bv.x, d.y*rs*gv.y + bv.y);
    orow[t*2+1] = __floats2half2_rn(d.z*rs*gv.z + bv.z, d.w*rs*gv.w + bv.w);
}

// ---------------- FP16 tensor-core GEMM NT (ldmatrix fragments) -------------
// C[N,M] = A[N,K] * B[M,K]^T.  128x128 tile, BK=32, 256 thr, 2x4 warps,
// 64x32/warp via 4x4 m16n8k16.  cp.async double-buffered, ldmatrix.x4 frags.
// EPI: 0=none, 1=+bias, 2=+res, 3=relu(+bias)+res.  HOUT: 1 = store half.
#define GLDSH 40   // 32 + 8 pad halves; 80B rows; stride-20-word: conflict-free

template<int EPI, int HOUT>
__global__ __launch_bounds__(256) void gemm_f16(const __half* __restrict__ A,
                                                const __half* __restrict__ B,
                                                void* __restrict__ Cv,
                                                int N, int M, int K,
                                                const float* __restrict__ bias,
                                                const float* __restrict__ res)
{
    __shared__ __align__(16) __half As[2][128][GLDSH];
    __shared__ __align__(16) __half Bs[2][128][GLDSH];

    const int t    = threadIdx.x;
    const int lane = t & 31;
    const int warp = t >> 5;
    const int wm   = warp >> 2;
    const int wn   = warp & 3;
    const int g    = lane >> 2;
    const int tig  = lane & 3;
    const int n0   = blockIdx.y * 128;
    const int m0   = blockIdx.x * 128;

    // ldmatrix lane->element maps
    const int a_row = lane & 15;
    const int a_col = (lane >> 4) << 3;
    const int b_row = ((lane >> 4) << 3) + (lane & 7);
    const int b_col = ((lane >> 3) & 1) << 3;

    const int lr = t >> 1;             // 0..127
    const int sg = (t & 1) * 16;       // 0 or 16 halves

    const __half* Ar = A + (size_t)(n0 + lr) * K + sg;
    const __half* Br = B + (size_t)(m0 + lr) * K + sg;

    float acc[4][4][4];
    #pragma unroll
    for (int i = 0; i < 4; i++)
        #pragma unroll
        for (int j = 0; j < 4; j++)
            #pragma unroll
            for (int c = 0; c < 4; c++) acc[i][j][c] = 0.f;

    const int nK = K / 32;

    {
        CP_ASYNC16(smem_u32(&As[0][lr][sg]),     Ar);
        CP_ASYNC16(smem_u32(&As[0][lr][sg + 8]), Ar + 8);
        CP_ASYNC16(smem_u32(&Bs[0][lr][sg]),     Br);
        CP_ASYNC16(smem_u32(&Bs[0][lr][sg + 8]), Br + 8);
        CP_COMMIT();
    }

    for (int kt = 0; kt < nK; kt++) {
        const int cur = kt & 1;
        if (kt + 1 < nK) {
            const int nxt = cur ^ 1;
            const int ko = (kt + 1) * 32;
            CP_ASYNC16(smem_u32(&As[nxt][lr][sg]),     Ar + ko);
            CP_ASYNC16(smem_u32(&As[nxt][lr][sg + 8]), Ar + ko + 8);
            CP_ASYNC16(smem_u32(&Bs[nxt][lr][sg]),     Br + ko);
            CP_ASYNC16(smem_u32(&Bs[nxt][lr][sg + 8]), Br + ko + 8);
            CP_COMMIT();
            CP_WAIT(1);
        } else {
            CP_WAIT(0);
        }
        __syncthreads();

        #pragma unroll
        for (int ks = 0; ks < 2; ks++) {
            const int kc = ks * 16;
            uint32_t af[4][4];
            #pragma unroll
            for (int mt = 0; mt < 4; mt++) {
                const int r = wm * 64 + mt * 16;
                LDMX4(af[mt][0], af[mt][1], af[mt][2], af[mt][3],
                      smem_u32(&As[cur][r + a_row][kc + a_col]));
            }
            uint32_t bf[4][2];
            #pragma unroll
            for (int p = 0; p < 2; p++) {
                const int c = wn * 32 + p * 16;
                uint32_t r0, r1, r2, r3;
                LDMX4(r0, r1, r2, r3,
                      smem_u32(&Bs[cur][c + b_row][kc + b_col]));
                bf[2*p][0] = r0; bf[2*p][1] = r1;
                bf[2*p+1][0] = r2; bf[2*p+1][1] = r3;
            }
            #pragma unroll
            for (int mt = 0; mt < 4; mt++)
                #pragma unroll
                for (int nt = 0; nt < 4; nt++)
                    MMA_F16(acc[mt][nt], af[mt], bf[nt]);
        }
        __syncthreads();
    }

    #pragma unroll
    for (int mt = 0; mt < 4; mt++) {
        const int r0 = n0 + wm * 64 + mt * 16 + g;
        #pragma unroll
        for (int nt = 0; nt < 4; nt++) {
            const int col = m0 + wn * 32 + nt * 8 + 2 * tig;
            float2 v0 = make_float2(acc[mt][nt][0], acc[mt][nt][1]);
            float2 v1 = make_float2(acc[mt][nt][2], acc[mt][nt][3]);
            if (EPI == 1 || EPI == 3) {
                float2 bb = *(const float2*)&bias[col];
                v0.x += bb.x; v0.y += bb.y;
                v1.x += bb.x; v1.y += bb.y;
            }
            if (EPI == 3) {
                v0.x = fmaxf(v0.x, 0.f); v0.y = fmaxf(v0.y, 0.f);
                v1.x = fmaxf(v1.x, 0.f); v1.y = fmaxf(v1.y, 0.f);
            }
            if (EPI == 2 || EPI == 3) {
                float2 r0v = *(const float2*)&res[(size_t)r0 * M + col];
                float2 r1v = *(const float2*)&res[(size_t)(r0 + 8) * M + col];
                v0.x += r0v.x; v0.y += r0v.y;
                v1.x += r1v.x; v1.y += r1v.y;
            }
            if (HOUT) {
                __half* C = (__half*)Cv;
                *(__half2*)&C[(size_t)r0 * M + col]       = __floats2half2_rn(v0.x, v0.y);
                *(__half2*)&C[(size_t)(r0 + 8) * M + col] = __floats2half2_rn(v1.x, v1.y);
            } else {
                float* C = (float*)Cv;
                *(float2*)&C[(size_t)r0 * M + col]       = v0;
                *(float2*)&C[(size_t)(r0 + 8) * M + col] = v1;
            }
        }
    }
}

// ---------------- FP16 tensor-core flash attention ---------------------------
// Reads Q/K/V from fused qkv buffer (row stride 3072).  128 q/CTA x 64-key
// tiles.  Q frags preloaded to regs; K/P frags via ldmatrix.x4; V via trans.
#define HQS  0
#define HKS  9216
#define HVS  18432
#define HPS  27648
#define HTOT 36864
#define AMSK_B (HTOT*2)
#define ASMEM_BYTES (AMSK_B + 2*64*4)
#define KSTG 4608

__global__ __launch_bounds__(256) void attn_tc(const __half* __restrict__ QKV,
                                               const unsigned char* __restrict__ mask,
                                               __half* __restrict__ O)
{
    extern __shared__ char shb[];
    __half* Qs  = (__half*)shb + HQS;
    __half* Ks  = (__half*)shb + HKS;
    __half* Vs  = (__half*)shb + HVS;
    __half* Ps  = (__half*)shb + HPS;
    float*  msk = (float*)(shb + AMSK_B);

    const int t    = threadIdx.x;
    const int lane = t & 31;
    const int warp = t >> 5;
    const int g    = lane >> 2;
    const int tig  = lane & 3;
    const int q0   = blockIdx.x * 128;
    const int h    = blockIdx.y;
    const int b    = blockIdx.z;
    const size_t baseQ = (size_t)b * SEQ * D3 + (size_t)h * DKH;
    const size_t baseK = baseQ + D_MODEL;
    const size_t baseV = baseQ + 2 * D_MODEL;
    const size_t baseO = (size_t)b * SEQ * D_MODEL + (size_t)h * DKH;
    const int rA = warp * 16 + g;

    const int a_row = lane & 15;
    const int a_col = (lane >> 4) << 3;
    const int b_row = ((lane >> 4) << 3) + (lane & 7);
    const int b_col = ((lane >> 3) & 1) << 3;

    // prologue: Q (128x64) + K/V tile 0 + mask
    #pragma unroll
    for (int i = 0; i < 4; i++) {
        int idx = t + i * 256, row = idx >> 3, s8 = (idx & 7) * 8;
        CP_ASYNC16(smem_u32(&Qs[row * 72 + s8]),
                   &QKV[baseQ + (size_t)(q0 + row) * D3 + s8]);
    }
    #pragma unroll
    for (int i = 0; i < 2; i++) {
        int idx = t + i * 256, row = idx >> 3, s8 = (idx & 7) * 8;
        CP_ASYNC16(smem_u32(&Ks[row * 72 + s8]),
                   &QKV[baseK + (size_t)row * D3 + s8]);
        CP_ASYNC16(smem_u32(&Vs[row * 72 + s8]),
                   &QKV[baseV + (size_t)row * D3 + s8]);
    }
    if (t < 64) msk[t] = mask[(size_t)b * SEQ + t] ? -3.0e38f : 0.f;
    CP_COMMIT();
    CP_WAIT(0);
    __syncthreads();

    // preload Q fragments (reused across all 32 key tiles)
    uint32_t qf[4][4];
    #pragma unroll
    for (int kc4 = 0; kc4 < 4; kc4++) {
        LDMX4(qf[kc4][0], qf[kc4][1], qf[kc4][2], qf[kc4][3],
              smem_u32(&Qs[(warp * 16 + a_row) * 72 + kc4 * 16 + a_col]));
    }

    float m0 = -3.0e38f, m1 = -3.0e38f, l0 = 0.f, l1 = 0.f;
    float oacc[8][4];
    #pragma unroll
    for (int nt = 0; nt < 8; nt++)
        #pragma unroll
        for (int c = 0; c < 4; c++) oacc[nt][c] = 0.f;

    const int ntiles = SEQ / 64;
    for (int kt = 0; kt < ntiles; kt++) {
        const int cur = kt & 1;
        const bool pref = (kt + 1 < ntiles);
        if (pref) {
            const int nxt = cur ^ 1;
            const int k0n = (kt + 1) * 64;
            #pragma unroll
            for (int i = 0; i < 2; i++) {
                int idx = t + i * 256, row = idx >> 3, s8 = (idx & 7) * 8;
                CP_ASYNC16(smem_u32(&Ks[nxt * KSTG + row * 72 + s8]),
                           &QKV[baseK + (size_t)(k0n + row) * D3 + s8]);
                CP_ASYNC16(smem_u32(&Vs[nxt * KSTG + row * 72 + s8]),
                           &QKV[baseV + (size_t)(k0n + row) * D3 + s8]);
            }
            if (t < 64) msk[(cur ^ 1) * 64 + t] =
                mask[(size_t)b * SEQ + k0n + t] ? -3.0e38f : 0.f;
            CP_COMMIT();
        }
        const __half* Kc = Ks + cur * KSTG;
        const __half* Vc = Vs + cur * KSTG;
        const float*  mc = msk + cur * 64;

        // ---- S = Q K^T ----
        float sc[8][4];
        #pragma unroll
        for (int nt = 0; nt < 8; nt++)
            #pragma unroll
            for (int c = 0; c < 4; c++) sc[nt][c] = 0.f;

        #pragma unroll
        for (int kc4 = 0; kc4 < 4; kc4++) {
            const int kc = kc4 * 16;
            #pragma unroll
            for (int p = 0; p < 4; p++) {
                const int c = p * 16;
                uint32_t r0, r1, r2, r3;
                LDMX4(r0, r1, r2, r3,
                      smem_u32(&Kc[(c + b_row) * 72 + kc + b_col]));
                uint32_t b0[2] = {r0, r1};
                uint32_t b1[2] = {r2, r3};
                MMA_F16(sc[2*p],     qf[kc4], b0);
                MMA_F16(sc[2*p + 1], qf[kc4], b1);
            }
        }

        // ---- scale + mask + row stats ----
        float tm0 = -3.0e38f, tm1 = -3.0e38f;
        #pragma unroll
        for (int nt = 0; nt < 8; nt++) {
            const float mk0 = mc[nt * 8 + 2 * tig];
            const float mk1 = mc[nt * 8 + 2 * tig + 1];
            sc[nt][0] = sc[nt][0] * 0.125f + mk0;
            sc[nt][1] = sc[nt][1] * 0.125f + mk1;
            sc[nt][2] = sc[nt][2] * 0.125f + mk0;
            sc[nt][3] = sc[nt][3] * 0.125f + mk1;
            tm0 = fmaxf(tm0, fmaxf(sc[nt][0], sc[nt][1]));
            tm1 = fmaxf(tm1, fmaxf(sc[nt][2], sc[nt][3]));
        }
        tm0 = fmaxf(tm0, __shfl_xor_sync(0xffffffffu, tm0, 1));
        tm0 = fmaxf(tm0, __shfl_xor_sync(0xffffffffu, tm0, 2));
        tm1 = fmaxf(tm1, __shfl_xor_sync(0xffffffffu, tm1, 1));
        tm1 = fmaxf(tm1, __shfl_xor_sync(0xffffffffu, tm1, 2));

        const float nm0 = fmaxf(m0, tm0), nm1 = fmaxf(m1, tm1);
        const float a0 = __expf(m0 - nm0), a1 = __expf(m1 - nm1);

        float ps0 = 0.f, ps1 = 0.f;
        #pragma unroll
        for (int nt = 0; nt < 8; nt++) {
            const float p0 = __expf(sc[nt][0] - nm0);
            const float p1 = __expf(sc[nt][1] - nm0);
            const float p2 = __expf(sc[nt][2] - nm1);
            const float p3 = __expf(sc[nt][3] - nm1);
            ps0 += p0 + p1; ps1 += p2 + p3;
            *(__half2*)&Ps[rA * 72 + nt * 8 + 2*tig]       = __floats2half2_rn(p0, p1);
            *(__half2*)&Ps[(rA + 8) * 72 + nt * 8 + 2*tig] = __floats2half2_rn(p2, p3);
        }
        ps0 += __shfl_xor_sync(0xffffffffu, ps0, 1);
        ps0 += __shfl_xor_sync(0xffffffffu, ps0, 2);
        ps1 += __shfl_xor_sync(0xffffffffu, ps1, 1);
        ps1 += __shfl_xor_sync(0xffffffffu, ps1, 2);

        l0 = l0 * a0 + ps0;  l1 = l1 * a1 + ps1;
        m0 = nm0;  m1 = nm1;
        #pragma unroll
        for (int nt = 0; nt < 8; nt++) {
            oacc[nt][0] *= a0; oacc[nt][1] *= a0;
            oacc[nt][2] *= a1; oacc[nt][3] *= a1;
        }
        __syncwarp();

        // ---- O += P V  (P via ldmatrix; V via ldmatrix.trans) ----
        const int mi = lane >> 3, rr = lane & 7;
        #pragma unroll
        for (int kc4 = 0; kc4 < 4; kc4++) {
            const int kc = kc4 * 16;
            uint32_t af[4];
            LDMX4(af[0], af[1], af[2], af[3],
                  smem_u32(&Ps[(warp * 16 + a_row) * 72 + kc + a_col]));
            #pragma unroll
            for (int ntp = 0; ntp < 4; ntp++) {
                const int key = kc + ((mi & 1) << 3) + rr;
                const int dim = ntp * 16 + ((mi >> 1) << 3);
                uint32_t r0, r1, r2, r3;
                LDMX4_TRANS(r0, r1, r2, r3, smem_u32(&Vc[key * 72 + dim]));
                uint32_t b0[2] = {r0, r1};
                uint32_t b1[2] = {r2, r3};
                MMA_F16(oacc[2*ntp],     af, b0);
                MMA_F16(oacc[2*ntp + 1], af, b1);
            }
        }

        if (pref) CP_WAIT(0);
        __syncthreads();
    }

    // ---- epilogue: normalize, store half ----
    const float i0 = 1.f / l0, i1 = 1.f / l1;
    #pragma unroll
    for (int nt = 0; nt < 8; nt++) {
        const int col = nt * 8 + 2 * tig;
        *(__half2*)&O[baseO + (size_t)(q0 + rA) * D_MODEL + col] =
            __floats2half2_rn(oacc[nt][0] * i0, oacc[nt][1] * i0);
        *(__half2*)&O[baseO + (size_t)(q0 + rA + 8) * D_MODEL + col] =
            __floats2half2_rn(oacc[nt][2] * i1, oacc[nt][3] * i1);
    }
}

// ---------------- launch ---------------------------------------------------
extern "C" void kernel_launch(void* const* d_in, const int* in_sizes, int n_in,
                              void* d_out, int out_size)
{
    const float* x     = (const float*)d_in[0];
    const unsigned char* mask = (const unsigned char*)d_in[1];
    const float* W_Q   = (const float*)d_in[2];
    const float* W_K   = (const float*)d_in[3];
    const float* W_V   = (const float*)d_in[4];
    const float* W_O   = (const float*)d_in[5];
    const float* W1    = (const float*)d_in[6];
    const float* b1    = (const float*)d_in[7];
    const float* W2    = (const float*)d_in[8];
    const float* b2    = (const float*)d_in[9];
    const float* g1    = (const float*)d_in[10];
    const float* beta1 = (const float*)d_in[11];
    const float* g2    = (const float*)d_in[12];
    const float* beta2 = (const float*)d_in[13];
    float* out = (float*)d_out;

    __half *h1, *qkv, *at, *h2, *f1;
    __half *wqkv, *wo, *w1, *w2;
    float *x1;
    cudaGetSymbolAddress((void**)&h1,   g_h1);
    cudaGetSymbolAddress((void**)&qkv,  g_qkv);
    cudaGetSymbolAddress((void**)&at,   g_at);
    cudaGetSymbolAddress((void**)&x1,   g_x1);
    cudaGetSymbolAddress((void**)&h2,   g_h2);
    cudaGetSymbolAddress((void**)&f1,   g_f1);
    cudaGetSymbolAddress((void**)&wqkv, g_wqkv);
    cudaGetSymbolAddress((void**)&wo,   g_wo);
    cudaGetSymbolAddress((void**)&w1,   g_w1);
    cudaGetSymbolAddress((void**)&w2,   g_w2);

    cudaFuncSetAttribute(attn_tc, cudaFuncAttributeMaxDynamicSharedMemorySize,
                         ASMEM_BYTES);

    const dim3 gQKV(D3/128,     NTOK/128);   // (24, 32)
    const dim3 gDD (D_MODEL/128, NTOK/128);  // (8, 32)
    const dim3 gDF (D_FF/128,    NTOK/128);  // (32, 32)
    const int DD4 = D_MODEL*D_MODEL/4, DF4 = D_FF*D_MODEL/4;

    // 0. weights -> fp16 (packed QKV + 3 singles)
    conv_qkv <<<3*DD4/256, 256>>>((const float4*)W_Q, (const float4*)W_K,
                                  (const float4*)W_V, wqkv);
    conv_half<<<(DD4+255)/256, 256>>>((const float4*)W_O, wo, DD4);
    conv_half<<<(DF4+255)/256, 256>>>((const float4*)W1,  w1, DF4);
    conv_half<<<(DF4+255)/256, 256>>>((const float4*)W2,  w2, DF4);

    // 1. pre-LN
    ln_kernel<<<NTOK, 256>>>(x, g1, beta1, h1);
    // 2. fused QKV projection (one GEMM, M=3072)
    gemm_f16<0,1><<<gQKV, 256>>>(h1, wqkv, qkv, NTOK, D3, D_MODEL, nullptr, nullptr);
    // 3. fp16 tensor-core flash attention
    attn_tc<<<dim3(SEQ/128, HEADS, BATCH), 256, ASMEM_BYTES>>>(qkv, mask, at);
    // 4. output projection + residual (fp32 out)
    gemm_f16<2,0><<<gDD, 256>>>(at, wo, x1, NTOK, D_MODEL, D_MODEL, nullptr, x);
    // 5. second LN
    ln_kernel<<<NTOK, 256>>>(x1, g2, beta2, h2);
    // 6. FFN1 (+b1)
    gemm_f16<1,1><<<gDF, 256>>>(h2, w1, f1, NTOK, D_FF, D_MODEL, b1, nullptr);
    // 7. FFN2: relu(C + b2) + residual(x1), fp32 final
    gemm_f16<3,0><<<gDD, 256>>>(f1, w2, out, NTOK, D_MODEL, D_FF, b2, x1);
}